// round 14
// baseline (speedup 1.0000x reference)
#include <cuda_runtime.h>
#include <cuda_fp16.h>
#include <stdint.h>

// CPQuadRankLayer via mma.sync fp16. B=64, N=1024, C=4, R=64, D=O=128.
// R12 + packed dual prefetch: x and f both prefetched as fp16x2 (16 regs each),
// residual accumulated in packed fp16 registers (no smem RMW). 256 thr, 2 CTAs/SM,
// warp tile 16b x 32r, acc untouched until epilogue. 1 MMA per k16 mainloop;
// epilogue GEMM 3-term fp16.

#define NN 1024

// smem byte offsets (mainloop)
#define XH_OFF   0        // 64 rows x 272B (128 fp16 + pad)
#define FH_OFF   17408
// epilogue overlay (over/after X/F region, all dead by then)
#define MH_OFF   0        // merged hi: 64 rows x 144B
#define ML_OFF   9216
#define FOH_OFF  18432    // fo^T hi: 128 rows x 144B
#define FOL_OFF  36864    // ends 55296
#define RES_OFF  55296    // res[b][o] f32: 64*128*4 = 32768
#define SS_OFF   88064    // ss[2][4][64] f32 = 2048
#define RINV_OFF 90112    // 64 f32
#define SMEM_BYTES 90368  // <= 113.5KB -> 2 CTAs/SM

__device__ __forceinline__ uint32_t packh2(float a, float b) {
    uint32_t r;   // low half = a, high half = b
    asm("cvt.rn.f16x2.f32 %0, %1, %2;" : "=r"(r) : "f"(b), "f"(a));
    return r;
}
__device__ __forceinline__ uint32_t haddx2(uint32_t a, uint32_t b) {
    uint32_t r;
    asm("add.rn.f16x2 %0, %1, %2;" : "=r"(r) : "r"(a), "r"(b));
    return r;
}
__device__ __forceinline__ float2 unpackh2(uint32_t v) {
    __half2 h = *reinterpret_cast<__half2*>(&v);
    return __half22float2(h);
}
__device__ __forceinline__ void splitf2(float a, float b, uint32_t& hi, uint32_t& lo) {
    __half ha = __float2half_rn(a), hb = __float2half_rn(b);
    hi = ((uint32_t)__half_as_ushort(hb) << 16) | (uint32_t)__half_as_ushort(ha);
    __half la = __float2half_rn(a - __half2float(ha));
    __half lb = __float2half_rn(b - __half2float(hb));
    lo = ((uint32_t)__half_as_ushort(lb) << 16) | (uint32_t)__half_as_ushort(la);
}
__device__ __forceinline__ void mma_f16(float* c, const uint32_t* a, const uint32_t* b) {
    asm volatile(
        "mma.sync.aligned.m16n8k16.row.col.f32.f16.f16.f32 "
        "{%0,%1,%2,%3}, {%4,%5,%6,%7}, {%8,%9}, {%0,%1,%2,%3};"
        : "+f"(c[0]), "+f"(c[1]), "+f"(c[2]), "+f"(c[3])
        : "r"(a[0]), "r"(a[1]), "r"(a[2]), "r"(a[3]), "r"(b[0]), "r"(b[1]));
}

__global__ __launch_bounds__(256, 2)
void cpquad_mma10(const float* __restrict__ x, const float* __restrict__ f,
                  const float* __restrict__ fo, const float* __restrict__ gain,
                  float* __restrict__ out)
{
    extern __shared__ char sm[];
    const int n = blockIdx.x;
    const int t = threadIdx.x;
    const int lane = t & 31, wid = t >> 5;
    const int g = lane >> 2, tg = lane & 3;
    const int wb = wid >> 1, ws = wid & 1;   // b-tile (16 rows), r-half (32)
    const int bb = wb * 16;
    const float gn = __ldg(&gain[n]);

    uint2 xr16[8], fr16[8], resh[8];
    float acc[4][4][4];
#pragma unroll
    for (int c = 0; c < 4; ++c)
#pragma unroll
        for (int nt = 0; nt < 4; ++nt)
#pragma unroll
            for (int u = 0; u < 4; ++u) acc[c][nt][u] = 0.0f;

    // prologue LDG+pack x(0), f(0): thread rows {wid+8j}, float4 col = lane
#pragma unroll
    for (int j = 0; j < 8; ++j) {
        float4 xv = *(const float4*)(x + (((size_t)(j * 8 + wid) * NN + n) * 4 + 0) * 128 + lane * 4);
        xr16[j].x = packh2(xv.x, xv.y);
        xr16[j].y = packh2(xv.z, xv.w);
        float4 fv = *(const float4*)(f + (((size_t)0 * NN + n) * 64 + (j * 8 + wid)) * 128 + lane * 4);
        fr16[j].x = packh2(fv.x, fv.y);
        fr16[j].y = packh2(fv.z, fv.w);
    }

#pragma unroll
    for (int c = 0; c < 4; ++c) {
        // STS both tiles from packed regs + packed residual accumulation
#pragma unroll
        for (int j = 0; j < 8; ++j) {
            const int row = j * 8 + wid;
            *(uint2*)(sm + XH_OFF + row * 272 + lane * 8) = xr16[j];
            *(uint2*)(sm + FH_OFF + row * 272 + lane * 8) = fr16[j];
            if (c == 0) resh[j] = xr16[j];
            else {
                resh[j].x = haddx2(resh[j].x, xr16[j].x);
                resh[j].y = haddx2(resh[j].y, xr16[j].y);
            }
        }
        __syncthreads();

        // prefetch BOTH x(c+1), f(c+1): LDG latency drains under the MMA block
        if (c < 3) {
#pragma unroll
            for (int j = 0; j < 8; ++j) {
                float4 xv = *(const float4*)(x + (((size_t)(j * 8 + wid) * NN + n) * 4 + (c + 1)) * 128 + lane * 4);
                xr16[j].x = packh2(xv.x, xv.y);
                xr16[j].y = packh2(xv.z, xv.w);
                float4 fv = *(const float4*)(f + (((size_t)(c + 1) * NN + n) * 64 + (j * 8 + wid)) * 128 + lane * 4);
                fr16[j].x = packh2(fv.x, fv.y);
                fr16[j].y = packh2(fv.z, fv.w);
            }
        }

        // projection MMAs: 16b x 32r per warp, K=128 (8 k16-steps), 1 MMA each
#pragma unroll
        for (int kk = 0; kk < 8; ++kk) {
            uint32_t ah[4];
            const uint32_t ab = (uint32_t)((bb + g) * 272 + kk * 32 + tg * 4);
            ah[0] = *(const uint32_t*)(sm + XH_OFF + ab);
            ah[1] = *(const uint32_t*)(sm + XH_OFF + ab + 2176);
            ah[2] = *(const uint32_t*)(sm + XH_OFF + ab + 16);
            ah[3] = *(const uint32_t*)(sm + XH_OFF + ab + 2192);
#pragma unroll
            for (int nt = 0; nt < 4; ++nt) {
                uint32_t bh[2];
                const uint32_t bby = (uint32_t)((ws * 32 + nt * 8 + g) * 272 + kk * 32 + tg * 4);
                bh[0] = *(const uint32_t*)(sm + FH_OFF + bby);
                bh[1] = *(const uint32_t*)(sm + FH_OFF + bby + 16);
                mma_f16(acc[c][nt], ah, bh);
            }
        }
        __syncthreads();
    }

    // ---- RMS partials + residual regs -> smem ----
#pragma unroll
    for (int c = 0; c < 4; ++c) {
        float s0 = 0.f, s1 = 0.f;
#pragma unroll
        for (int nt = 0; nt < 4; ++nt) {
            s0 = fmaf(acc[c][nt][0], acc[c][nt][0], s0);
            s0 = fmaf(acc[c][nt][1], acc[c][nt][1], s0);
            s1 = fmaf(acc[c][nt][2], acc[c][nt][2], s1);
            s1 = fmaf(acc[c][nt][3], acc[c][nt][3], s1);
        }
        s0 += __shfl_xor_sync(0xffffffffu, s0, 1);
        s0 += __shfl_xor_sync(0xffffffffu, s0, 2);
        s1 += __shfl_xor_sync(0xffffffffu, s1, 1);
        s1 += __shfl_xor_sync(0xffffffffu, s1, 2);
        if (tg == 0) {
            *(float*)(sm + SS_OFF + (((ws * 4 + c) * 64) + bb + g) * 4)     = s0;
            *(float*)(sm + SS_OFF + (((ws * 4 + c) * 64) + bb + g + 8) * 4) = s1;
        }
    }
#pragma unroll
    for (int j = 0; j < 8; ++j) {
        const int row = j * 8 + wid;
        float2 a = unpackh2(resh[j].x);
        float2 b = unpackh2(resh[j].y);
        *(float4*)(sm + RES_OFF + row * 512 + lane * 16) = make_float4(a.x, a.y, b.x, b.y);
    }
    __syncthreads();

    // rinv-product per b (first 64 threads) + fo^T gather/split/STS (all threads)
    if (t < 64) {
        float p = gn;
#pragma unroll
        for (int c = 0; c < 4; ++c) {
            float s = *(const float*)(sm + SS_OFF + ((0 * 4 + c) * 64 + t) * 4)
                    + *(const float*)(sm + SS_OFF + ((1 * 4 + c) * 64 + t) * 4);
            p *= rsqrtf(s * 0.015625f + 1e-6f);
        }
        *(float*)(sm + RINV_OFF + t * 4) = p;
    }
    {
        const int o = t >> 1, rh = (t & 1) * 32;
        const float* fob = fo + (size_t)n * 8192 + o;
#pragma unroll
        for (int u = 0; u < 8; ++u) {
            const int r0 = rh + u * 4;
            float v0 = fob[(r0 + 0) * 128], v1 = fob[(r0 + 1) * 128];
            float v2 = fob[(r0 + 2) * 128], v3 = fob[(r0 + 3) * 128];
            uint2 hi, lo;
            splitf2(v0, v1, hi.x, lo.x);
            splitf2(v2, v3, hi.y, lo.y);
            *(uint2*)(sm + FOH_OFF + o * 144 + r0 * 2) = hi;
            *(uint2*)(sm + FOL_OFF + o * 144 + r0 * 2) = lo;
        }
    }
    __syncthreads();

    // merged = prod_c P * rinvprod  -> fp16 hi/lo tile [b][r]
    {
        const float r0v = *(const float*)(sm + RINV_OFF + (bb + g) * 4);
        const float r1v = *(const float*)(sm + RINV_OFF + (bb + g + 8) * 4);
#pragma unroll
        for (int nt = 0; nt < 4; ++nt) {
            const int rc = ws * 32 + nt * 8 + tg * 2;
            float m0 = acc[0][nt][0] * acc[1][nt][0] * acc[2][nt][0] * acc[3][nt][0] * r0v;
            float m1 = acc[0][nt][1] * acc[1][nt][1] * acc[2][nt][1] * acc[3][nt][1] * r0v;
            float m2 = acc[0][nt][2] * acc[1][nt][2] * acc[2][nt][2] * acc[3][nt][2] * r1v;
            float m3 = acc[0][nt][3] * acc[1][nt][3] * acc[2][nt][3] * acc[3][nt][3] * r1v;
            uint32_t h01, l01, h23, l23;
            splitf2(m0, m1, h01, l01);
            splitf2(m2, m3, h23, l23);
            *(uint32_t*)(sm + MH_OFF + (bb + g) * 144 + rc * 2)     = h01;
            *(uint32_t*)(sm + ML_OFF + (bb + g) * 144 + rc * 2)     = l01;
            *(uint32_t*)(sm + MH_OFF + (bb + g + 8) * 144 + rc * 2) = h23;
            *(uint32_t*)(sm + ML_OFF + (bb + g + 8) * 144 + rc * 2) = l23;
        }
    }
    __syncthreads();

    // output GEMM: warp = (wb, o-half ws): 16b x 64o, K=64 (4 k16-steps), 3 terms
    float acc2[8][4];
#pragma unroll
    for (int nt = 0; nt < 8; ++nt)
#pragma unroll
        for (int u = 0; u < 4; ++u) acc2[nt][u] = 0.0f;

    const int obase = ws * 64;
#pragma unroll
    for (int kk = 0; kk < 4; ++kk) {
        uint32_t ah[4], al[4];
        const uint32_t ab = (uint32_t)((bb + g) * 144 + kk * 32 + tg * 4);
        ah[0] = *(const uint32_t*)(sm + MH_OFF + ab);
        ah[1] = *(const uint32_t*)(sm + MH_OFF + ab + 1152);
        ah[2] = *(const uint32_t*)(sm + MH_OFF + ab + 16);
        ah[3] = *(const uint32_t*)(sm + MH_OFF + ab + 1168);
        al[0] = *(const uint32_t*)(sm + ML_OFF + ab);
        al[1] = *(const uint32_t*)(sm + ML_OFF + ab + 1152);
        al[2] = *(const uint32_t*)(sm + ML_OFF + ab + 16);
        al[3] = *(const uint32_t*)(sm + ML_OFF + ab + 1168);
#pragma unroll
        for (int nt = 0; nt < 8; ++nt) {
            uint32_t bh[2], bl[2];
            const uint32_t bby = (uint32_t)((obase + nt * 8 + g) * 144 + kk * 32 + tg * 4);
            bh[0] = *(const uint32_t*)(sm + FOH_OFF + bby);
            bh[1] = *(const uint32_t*)(sm + FOH_OFF + bby + 16);
            bl[0] = *(const uint32_t*)(sm + FOL_OFF + bby);
            bl[1] = *(const uint32_t*)(sm + FOL_OFF + bby + 16);
            mma_f16(acc2[nt], ah, bh);
            mma_f16(acc2[nt], ah, bl);
            mma_f16(acc2[nt], al, bh);
        }
    }

    // store with residual mean (res from smem)
#pragma unroll
    for (int nt = 0; nt < 8; ++nt) {
        const int oc = obase + nt * 8 + tg * 2;
        const int b0 = bb + g, b1 = bb + g + 8;
        const float2 r0 = *(const float2*)(sm + RES_OFF + (b0 * 128 + oc) * 4);
        const float2 r1 = *(const float2*)(sm + RES_OFF + (b1 * 128 + oc) * 4);
        float2 o0, o1;
        o0.x = acc2[nt][0] + 0.25f * r0.x;
        o0.y = acc2[nt][1] + 0.25f * r0.y;
        o1.x = acc2[nt][2] + 0.25f * r1.x;
        o1.y = acc2[nt][3] + 0.25f * r1.y;
        *(float2*)(out + ((size_t)b0 * NN + n) * 128 + oc) = o0;
        *(float2*)(out + ((size_t)b1 * NN + n) * 128 + oc) = o1;
    }
}

extern "C" void kernel_launch(void* const* d_in, const int* in_sizes, int n_in,
                              void* d_out, int out_size)
{
    const float* x       = (const float*)d_in[0];
    const float* factors = (const float*)d_in[1];
    const float* fo      = (const float*)d_in[2];
    const float* gain    = (const float*)d_in[3];
    float* out = (float*)d_out;

    cudaFuncSetAttribute(cpquad_mma10, cudaFuncAttributeMaxDynamicSharedMemorySize, SMEM_BYTES);
    cpquad_mma10<<<NN, 256, SMEM_BYTES>>>(x, factors, fo, gain, out);
}

// round 15
// speedup vs baseline: 1.0873x; 1.0873x over previous
#include <cuda_runtime.h>
#include <cuda_fp16.h>
#include <stdint.h>

// CPQuadRankLayer via mma.sync fp16. B=64, N=1024, C=4, R=64, D=O=128.
// R12 structure frozen (256 thr, 2 CTAs/SM, warp tile 16b x 32r, x-prefetch,
// f LDG at stage start, smem f32 residual RMW, acc untouched until epilogue).
// Work cuts: ldmatrix.x4 fragment loads (main + epilogue), 2-term epilogue
// (merged hi/lo x single-fp16 fo).

#define NN 1024

// smem byte offsets (mainloop)
#define XH_OFF   0        // 64 rows x 272B (128 fp16 + pad)
#define FH_OFF   17408
// epilogue overlay (over X/F region, dead after mainloop)
#define MH_OFF   0        // merged hi: 64 rows x 144B
#define ML_OFF   9216     // merged lo
#define FOH_OFF  18432    // fo^T: 128 rows x 144B -> ends 36864
#define RES_OFF  36864    // res[b][o] f32 accum: 64*128*4 = 32768 (live in mainloop)
#define SS_OFF   69632    // ss[2][4][64] f32 = 2048
#define RINV_OFF 71680    // 64 f32
#define SMEM_BYTES 71936  // 2 CTAs/SM (regs are the cap anyway)

__device__ __forceinline__ uint32_t smem_u32(const void* p) {
    uint32_t a;
    asm("{ .reg .u64 t; cvta.to.shared.u64 t, %1; cvt.u32.u64 %0, t; }" : "=r"(a) : "l"(p));
    return a;
}
__device__ __forceinline__ uint32_t packh2(float a, float b) {
    uint32_t r;   // low half = a, high half = b
    asm("cvt.rn.f16x2.f32 %0, %1, %2;" : "=r"(r) : "f"(b), "f"(a));
    return r;
}
__device__ __forceinline__ void splitf2(float a, float b, uint32_t& hi, uint32_t& lo) {
    __half ha = __float2half_rn(a), hb = __float2half_rn(b);
    hi = ((uint32_t)__half_as_ushort(hb) << 16) | (uint32_t)__half_as_ushort(ha);
    __half la = __float2half_rn(a - __half2float(ha));
    __half lb = __float2half_rn(b - __half2float(hb));
    lo = ((uint32_t)__half_as_ushort(lb) << 16) | (uint32_t)__half_as_ushort(la);
}
__device__ __forceinline__ void mma_f16(float* c, const uint32_t* a, const uint32_t* b) {
    asm volatile(
        "mma.sync.aligned.m16n8k16.row.col.f32.f16.f16.f32 "
        "{%0,%1,%2,%3}, {%4,%5,%6,%7}, {%8,%9}, {%0,%1,%2,%3};"
        : "+f"(c[0]), "+f"(c[1]), "+f"(c[2]), "+f"(c[3])
        : "r"(a[0]), "r"(a[1]), "r"(a[2]), "r"(a[3]), "r"(b[0]), "r"(b[1]));
}
__device__ __forceinline__ void ldm_x4(uint32_t* r, uint32_t addr) {
    asm volatile("ldmatrix.sync.aligned.m8n8.x4.shared.b16 {%0,%1,%2,%3}, [%4];"
                 : "=r"(r[0]), "=r"(r[1]), "=r"(r[2]), "=r"(r[3]) : "r"(addr));
}

__global__ __launch_bounds__(256, 2)
void cpquad_mma11(const float* __restrict__ x, const float* __restrict__ f,
                  const float* __restrict__ fo, const float* __restrict__ gain,
                  float* __restrict__ out)
{
    extern __shared__ char sm[];
    const int n = blockIdx.x;
    const int t = threadIdx.x;
    const int lane = t & 31, wid = t >> 5;
    const int g = lane >> 2, tg = lane & 3;
    const int wb = wid >> 1, ws = wid & 1;   // b-tile (16 rows), r-half (32)
    const int bb = wb * 16;
    const uint32_t smb = smem_u32(sm);
    const float gn = __ldg(&gain[n]);

    // ldmatrix lane-address bases (tiles T00,T10,T01,T11 order)
    const uint32_t aBase = smb + XH_OFF + (uint32_t)(bb + (lane & 15)) * 272
                           + (uint32_t)((lane >> 4) << 4);
    const uint32_t bRow  = (uint32_t)(ws * 32 + (lane & 7) + ((lane >> 4) & 1) * 8);
    const uint32_t bCol  = (uint32_t)(((lane >> 3) & 1) << 4);
    const uint32_t bBase0 = smb + FH_OFF + bRow * 272 + bCol;   // nt pair 0 (nt 0,1)
    const uint32_t bBase1 = bBase0 + 16 * 272;                  // nt pair 1 (nt 2,3)

    float4 xr[8];
    float acc[4][4][4];
#pragma unroll
    for (int c = 0; c < 4; ++c)
#pragma unroll
        for (int nt = 0; nt < 4; ++nt)
#pragma unroll
            for (int u = 0; u < 4; ++u) acc[c][nt][u] = 0.0f;

    // prologue LDG x(0): thread rows {wid+8j}, float4 col = lane
#pragma unroll
    for (int j = 0; j < 8; ++j)
        xr[j] = *(const float4*)(x + (((size_t)(j * 8 + wid) * NN + n) * 4 + 0) * 128 + lane * 4);

#pragma unroll
    for (int c = 0; c < 4; ++c) {
        // issue f(c) LDGs early, then x STS + residual RMW while f is in flight
        float4 fr[8];
#pragma unroll
        for (int j = 0; j < 8; ++j)
            fr[j] = *(const float4*)(f + (((size_t)c * NN + n) * 64 + (j * 8 + wid)) * 128 + lane * 4);

#pragma unroll
        for (int j = 0; j < 8; ++j) {
            const int row = j * 8 + wid;
            uint2 hi;
            hi.x = packh2(xr[j].x, xr[j].y);
            hi.y = packh2(xr[j].z, xr[j].w);
            *(uint2*)(sm + XH_OFF + row * 272 + lane * 8) = hi;
            float4* rp = (float4*)(sm + RES_OFF + row * 512 + lane * 16);
            if (c == 0) *rp = xr[j];
            else {
                float4 o = *rp;
                o.x += xr[j].x; o.y += xr[j].y; o.z += xr[j].z; o.w += xr[j].w;
                *rp = o;
            }
        }
#pragma unroll
        for (int j = 0; j < 8; ++j) {
            const int row = j * 8 + wid;
            uint2 hi;
            hi.x = packh2(fr[j].x, fr[j].y);
            hi.y = packh2(fr[j].z, fr[j].w);
            *(uint2*)(sm + FH_OFF + row * 272 + lane * 8) = hi;
        }
        __syncthreads();

        // prefetch x(c+1): latency hides under the MMA block
        if (c < 3) {
#pragma unroll
            for (int j = 0; j < 8; ++j)
                xr[j] = *(const float4*)(x + (((size_t)(j * 8 + wid) * NN + n) * 4 + (c + 1)) * 128 + lane * 4);
        }

        // projection MMAs: 16b x 32r per warp, K=128; ldmatrix fragments
#pragma unroll
        for (int kk = 0; kk < 8; ++kk) {
            uint32_t ah[4], b0[4], b1[4];
            ldm_x4(ah, aBase + kk * 32);
            ldm_x4(b0, bBase0 + kk * 32);
            mma_f16(acc[c][0], ah, b0);
            mma_f16(acc[c][1], ah, b0 + 2);
            ldm_x4(b1, bBase1 + kk * 32);
            mma_f16(acc[c][2], ah, b1);
            mma_f16(acc[c][3], ah, b1 + 2);
        }
        __syncthreads();
    }

    // ---- RMS partials: lane rows g, g+8; reduce over the 4 tg lanes ----
#pragma unroll
    for (int c = 0; c < 4; ++c) {
        float s0 = 0.f, s1 = 0.f;
#pragma unroll
        for (int nt = 0; nt < 4; ++nt) {
            s0 = fmaf(acc[c][nt][0], acc[c][nt][0], s0);
            s0 = fmaf(acc[c][nt][1], acc[c][nt][1], s0);
            s1 = fmaf(acc[c][nt][2], acc[c][nt][2], s1);
            s1 = fmaf(acc[c][nt][3], acc[c][nt][3], s1);
        }
        s0 += __shfl_xor_sync(0xffffffffu, s0, 1);
        s0 += __shfl_xor_sync(0xffffffffu, s0, 2);
        s1 += __shfl_xor_sync(0xffffffffu, s1, 1);
        s1 += __shfl_xor_sync(0xffffffffu, s1, 2);
        if (tg == 0) {
            *(float*)(sm + SS_OFF + (((ws * 4 + c) * 64) + bb + g) * 4)     = s0;
            *(float*)(sm + SS_OFF + (((ws * 4 + c) * 64) + bb + g + 8) * 4) = s1;
        }
    }
    __syncthreads();

    // rinv-product per b (first 64 threads) + fo^T gather (single fp16) + STS
    if (t < 64) {
        float p = gn;
#pragma unroll
        for (int c = 0; c < 4; ++c) {
            float s = *(const float*)(sm + SS_OFF + ((0 * 4 + c) * 64 + t) * 4)
                    + *(const float*)(sm + SS_OFF + ((1 * 4 + c) * 64 + t) * 4);
            p *= rsqrtf(s * 0.015625f + 1e-6f);
        }
        *(float*)(sm + RINV_OFF + t * 4) = p;
    }
    {
        const int o = t >> 1, rh = (t & 1) * 32;
        const float* fob = fo + (size_t)n * 8192 + o;
#pragma unroll
        for (int u = 0; u < 8; ++u) {
            const int r0 = rh + u * 4;
            uint2 hi;
            hi.x = packh2(fob[(r0 + 0) * 128], fob[(r0 + 1) * 128]);
            hi.y = packh2(fob[(r0 + 2) * 128], fob[(r0 + 3) * 128]);
            *(uint2*)(sm + FOH_OFF + o * 144 + r0 * 2) = hi;
        }
    }
    __syncthreads();

    // merged = prod_c P * rinvprod  -> fp16 hi/lo tile [b][r]
    {
        const float r0v = *(const float*)(sm + RINV_OFF + (bb + g) * 4);
        const float r1v = *(const float*)(sm + RINV_OFF + (bb + g + 8) * 4);
#pragma unroll
        for (int nt = 0; nt < 4; ++nt) {
            const int rc = ws * 32 + nt * 8 + tg * 2;
            float m0 = acc[0][nt][0] * acc[1][nt][0] * acc[2][nt][0] * acc[3][nt][0] * r0v;
            float m1 = acc[0][nt][1] * acc[1][nt][1] * acc[2][nt][1] * acc[3][nt][1] * r0v;
            float m2 = acc[0][nt][2] * acc[1][nt][2] * acc[2][nt][2] * acc[3][nt][2] * r1v;
            float m3 = acc[0][nt][3] * acc[1][nt][3] * acc[2][nt][3] * acc[3][nt][3] * r1v;
            uint32_t h01, l01, h23, l23;
            splitf2(m0, m1, h01, l01);
            splitf2(m2, m3, h23, l23);
            *(uint32_t*)(sm + MH_OFF + (bb + g) * 144 + rc * 2)     = h01;
            *(uint32_t*)(sm + ML_OFF + (bb + g) * 144 + rc * 2)     = l01;
            *(uint32_t*)(sm + MH_OFF + (bb + g + 8) * 144 + rc * 2) = h23;
            *(uint32_t*)(sm + ML_OFF + (bb + g + 8) * 144 + rc * 2) = l23;
        }
    }
    __syncthreads();

    // output GEMM: warp (wb, ws): 16b x 64o, K=64, 2 terms ((mh+ml) x foh)
    float acc2[8][4];
#pragma unroll
    for (int nt = 0; nt < 8; ++nt)
#pragma unroll
        for (int u = 0; u < 4; ++u) acc2[nt][u] = 0.0f;

    const int obase = ws * 64;
    const uint32_t mBase  = smb + MH_OFF + (uint32_t)(bb + (lane & 15)) * 144
                            + (uint32_t)((lane >> 4) << 4);
    const uint32_t mlBase = mBase + (ML_OFF - MH_OFF);
    const uint32_t foRow  = (uint32_t)(obase + (lane & 7) + ((lane >> 4) & 1) * 8);
    const uint32_t foBase = smb + FOH_OFF + foRow * 144 + (uint32_t)(((lane >> 3) & 1) << 4);

#pragma unroll
    for (int kk = 0; kk < 4; ++kk) {
        uint32_t ah[4], al[4];
        ldm_x4(ah, mBase + kk * 32);
        ldm_x4(al, mlBase + kk * 32);
#pragma unroll
        for (int p = 0; p < 4; ++p) {
            uint32_t bq[4];
            ldm_x4(bq, foBase + (uint32_t)(p * 16 * 144) + kk * 32);
            mma_f16(acc2[2 * p],     ah, bq);
            mma_f16(acc2[2 * p],     al, bq);
            mma_f16(acc2[2 * p + 1], ah, bq + 2);
            mma_f16(acc2[2 * p + 1], al, bq + 2);
        }
    }

    // store with residual mean (res from smem accumulator)
#pragma unroll
    for (int nt = 0; nt < 8; ++nt) {
        const int oc = obase + nt * 8 + tg * 2;
        const int b0 = bb + g, b1 = bb + g + 8;
        const float2 r0 = *(const float2*)(sm + RES_OFF + (b0 * 128 + oc) * 4);
        const float2 r1 = *(const float2*)(sm + RES_OFF + (b1 * 128 + oc) * 4);
        float2 o0, o1;
        o0.x = acc2[nt][0] + 0.25f * r0.x;
        o0.y = acc2[nt][1] + 0.25f * r0.y;
        o1.x = acc2[nt][2] + 0.25f * r1.x;
        o1.y = acc2[nt][3] + 0.25f * r1.y;
        *(float2*)(out + ((size_t)b0 * NN + n) * 128 + oc) = o0;
        *(float2*)(out + ((size_t)b1 * NN + n) * 128 + oc) = o1;
    }
}

extern "C" void kernel_launch(void* const* d_in, const int* in_sizes, int n_in,
                              void* d_out, int out_size)
{
    const float* x       = (const float*)d_in[0];
    const float* factors = (const float*)d_in[1];
    const float* fo      = (const float*)d_in[2];
    const float* gain    = (const float*)d_in[3];
    float* out = (float*)d_out;

    cudaFuncSetAttribute(cpquad_mma11, cudaFuncAttributeMaxDynamicSharedMemorySize, SMEM_BYTES);
    cpquad_mma11<<<NN, 256, SMEM_BYTES>>>(x, factors, fo, gain, out);
}